// round 16
// baseline (speedup 1.0000x reference)
#include <cuda_runtime.h>
#include <cuda_bf16.h>
#include <stdint.h>

// Problem shapes (fixed by the reference)
#define D_K      128
#define SEQ_LEN  4096
#define BATCH    4
#define N_HEADS  16
#define N_ROWS   (BATCH * N_HEADS)           // 64 (b,h) rows
#define VEC4_PER_ROW 32                      // 128 floats / 4
#define ROW_STRIDE_V4 (SEQ_LEN * VEC4_PER_ROW)   // 131072 vec4 between rows

#define THREADS     512
#define WARPS       (THREADS / 32)           // 16
#define CHUNK_POS   64                       // positions per block
#define ITERS       (CHUNK_POS / WARPS)      // 4
#define N_CHUNKS    (SEQ_LEN / CHUNK_POS)    // 64
// grid = N_ROWS * N_CHUNKS = 4096 blocks; each block streams a contiguous
// 32 KB slice of x (and out): row r, positions [c*64, c*64+64).

// ---------------------------------------------------------------------------
// Barrier-free fused RoPE.
//
// Table trick: the block-diagonal rotation matrix stores, in row 2k+1,
//   R[pos, 2k+1, 2k]   = sin_k
//   R[pos, 2k+1, 2k+1] = cos_k      (adjacent, row-major!)
// so ONE float2 load at float-offset  pos*16384 + 258*k + 128  yields
// {sin_k, cos_k} in a single 32B sector — half the gather sectors of the
// diagonal+subdiagonal scheme.
//
// Mapping: warp w of block (r, c) at iteration i handles position
//   p = c*64 + i*16 + w   — the warp's 32 lanes cover that position's whole
// 128-float row of x (one float4 per lane, 512 B coalesced). Lane l needs
// exactly rotation pairs k=2l and k=2l+1 → two float2 table loads, values
// land directly in the consuming thread: no smem, no __syncthreads.
// Table lines are L2-resident after the first of the 64 row-blocks per
// chunk touches them. x/out use streaming (.cs) hints to keep the table
// from being evicted by the 256 MB stream.
// ---------------------------------------------------------------------------
__global__ void __launch_bounds__(THREADS) rope_fused_kernel(
    const float4* __restrict__ x4,
    float4* __restrict__ out4,
    const float* __restrict__ ro_weights,
    const int* __restrict__ token_positions)
{
    const int r    = blockIdx.x >> 6;        // (b,h) row        0..63
    const int c    = blockIdx.x & 63;        // position chunk   0..63
    const int w    = threadIdx.x >> 5;       // warp             0..15
    const int lane = threadIdx.x & 31;

    const float2* tbl2 = reinterpret_cast<const float2*>(ro_weights);

    int   p[ITERS];
    int   idx[ITERS];
    float4 v[ITERS];
    float2 f0[ITERS], f1[ITERS];

    // ---- front-batch everything independent (MLP = 12) ----
#pragma unroll
    for (int i = 0; i < ITERS; i++) {
        p[i]   = c * CHUNK_POS + i * WARPS + w;
        idx[i] = r * ROW_STRIDE_V4 + p[i] * VEC4_PER_ROW + lane;
        v[i]   = __ldcs(x4 + idx[i]);                       // streaming read
    }
#pragma unroll
    for (int i = 0; i < ITERS; i++) {
        int pos = __ldg(token_positions + p[i]);            // warp-uniform
        // float-offset of {sin_k, cos_k}: pos*16384 + 258*k + 128, as float2
        // index: (pos*16384 + 258*k + 128) / 2 = pos*8192 + 129*k + 64
        int tb = pos * (D_K * D_K / 2) + 64;
        int k0 = 2 * lane;
        f0[i] = __ldg(tbl2 + tb + 129 * k0);                // {sin, cos} k=2l
        f1[i] = __ldg(tbl2 + tb + 129 * (k0 + 1));          // {sin, cos} k=2l+1
    }

    // ---- rotate + streaming store ----
#pragma unroll
    for (int i = 0; i < ITERS; i++) {
        float4 rv;
        rv.x = f0[i].y * v[i].x - f0[i].x * v[i].y;         // cos*xe - sin*xo
        rv.y = f0[i].x * v[i].x + f0[i].y * v[i].y;         // sin*xe + cos*xo
        rv.z = f1[i].y * v[i].z - f1[i].x * v[i].w;
        rv.w = f1[i].x * v[i].z + f1[i].y * v[i].w;
        __stcs(out4 + idx[i], rv);                          // streaming write
    }
}

// ---------------------------------------------------------------------------
// Launch. Inputs (metadata order): x [B,H,S,D] f32, token_positions [S] i32,
// ro_weights [4096,128,128] f32. Output: [B,H,S,D] f32.
// ---------------------------------------------------------------------------
extern "C" void kernel_launch(void* const* d_in, const int* in_sizes, int n_in,
                              void* d_out, int out_size)
{
    const float* x          = (const float*)d_in[0];
    const int*   tok_pos    = (const int*)d_in[1];
    const float* ro_weights = (const float*)d_in[2];

    rope_fused_kernel<<<N_ROWS * N_CHUNKS, THREADS>>>(
        reinterpret_cast<const float4*>(x),
        reinterpret_cast<float4*>((float*)d_out),
        ro_weights,
        tok_pos);
}

// round 17
// speedup vs baseline: 1.5647x; 1.5647x over previous
#include <cuda_runtime.h>
#include <cuda_bf16.h>
#include <stdint.h>

// Problem shapes (fixed by the reference)
#define D_K      128
#define HALF_D   64
#define SEQ_LEN  4096
#define BATCH    4
#define N_HEADS  16
#define N_ROWS   (BATCH * N_HEADS)        // 64 rows (b,h) per position s
#define VEC4_PER_ROW 32                   // 128 floats / 4
#define ROW_STRIDE_V4 (SEQ_LEN * VEC4_PER_ROW)  // 131072 vec4 between (b,h) rows

#define THREADS 512
#define ROWS_PER_ITER (THREADS / 32)      // 16 rows covered per pass

// ---------------------------------------------------------------------------
// Fused kernel: one block per position s.  (R6 structure — measured 47.3us,
// DRAM 76.3% — with the gather phase upgraded to float2 loads.)
//
// Phase 1: threads 0..63 each load ONE float2 from row 2k+1 of the rotation
//   matrix, where sin_k (col 2k) and cos_k (col 2k+1) are ADJACENT row-major:
//     float offset = pos*16384 + (2t+1)*128 + 2t = pos*16384 + 258t + 128
//   (even → 8B aligned). This is 64 sectors/position instead of 128 —
//   halves gather DRAM vs the per-float scheme. The {sin,cos} pair is
//   stored swapped into smem, giving interleaved {cos0,sin0,cos1,sin1,...}
//   so a float4 read at vec4-column c yields two rotation pairs.
//
// Phase 2 (unchanged from R6): stream all 64 (b,h) rows for this s. Each
//   warp covers one row's 512 contiguous bytes; each thread keeps a fixed
//   column (one smem read). The 4 x-loads (rows w, w+16, w+32, w+48 —
//   32 MB apart, independent) are front-batched for MLP=4.
// ---------------------------------------------------------------------------
__global__ void __launch_bounds__(THREADS) rope_fused_kernel(
    const float4* __restrict__ x4,
    float4* __restrict__ out4,
    const float* __restrict__ ro_weights,
    const int* __restrict__ token_positions)
{
    __shared__ float2 cs_s[HALF_D];       // {cos_k, sin_k} per rotation pair

    const int s   = blockIdx.x;
    const int tid = threadIdx.x;

    // ---- Phase 1: gather cos/sin for this position (64 float2 loads) ----
    if (tid < HALF_D) {
        int pos = token_positions[s];                       // broadcast load
        size_t off = (size_t)pos * (D_K * D_K) + 258 * tid + D_K;
        float2 sc = __ldg(reinterpret_cast<const float2*>(ro_weights + off));
        cs_s[tid] = make_float2(sc.y, sc.x);                // {cos, sin}
    }
    __syncthreads();

    // ---- Phase 2: stream the 64 rows ----
    const int col = tid & 31;          // fixed vec4 column for this thread
    const int w   = tid >> 5;          // warp id = row offset within pass

    const float4* cs4 = reinterpret_cast<const float4*>(cs_s);
    const float4 cs = cs4[col];        // {c0, s0, c1, s1}

    // base vec4 index for row r: r*ROW_STRIDE_V4 + s*32 + col
    const int base = w * ROW_STRIDE_V4 + s * VEC4_PER_ROW + col;

    // Batch all 4 independent x-loads (MLP=4)
    float4 v0 = x4[base + 0 * ROWS_PER_ITER * ROW_STRIDE_V4];
    float4 v1 = x4[base + 1 * ROWS_PER_ITER * ROW_STRIDE_V4];
    float4 v2 = x4[base + 2 * ROWS_PER_ITER * ROW_STRIDE_V4];
    float4 v3 = x4[base + 3 * ROWS_PER_ITER * ROW_STRIDE_V4];

    float4 r0, r1, r2, r3;
    r0.x = cs.x * v0.x - cs.y * v0.y;  r0.y = cs.y * v0.x + cs.x * v0.y;
    r0.z = cs.z * v0.z - cs.w * v0.w;  r0.w = cs.w * v0.z + cs.z * v0.w;

    r1.x = cs.x * v1.x - cs.y * v1.y;  r1.y = cs.y * v1.x + cs.x * v1.y;
    r1.z = cs.z * v1.z - cs.w * v1.w;  r1.w = cs.w * v1.z + cs.z * v1.w;

    r2.x = cs.x * v2.x - cs.y * v2.y;  r2.y = cs.y * v2.x + cs.x * v2.y;
    r2.z = cs.z * v2.z - cs.w * v2.w;  r2.w = cs.w * v2.z + cs.z * v2.w;

    r3.x = cs.x * v3.x - cs.y * v3.y;  r3.y = cs.y * v3.x + cs.x * v3.y;
    r3.z = cs.z * v3.z - cs.w * v3.w;  r3.w = cs.w * v3.z + cs.z * v3.w;

    out4[base + 0 * ROWS_PER_ITER * ROW_STRIDE_V4] = r0;
    out4[base + 1 * ROWS_PER_ITER * ROW_STRIDE_V4] = r1;
    out4[base + 2 * ROWS_PER_ITER * ROW_STRIDE_V4] = r2;
    out4[base + 3 * ROWS_PER_ITER * ROW_STRIDE_V4] = r3;
}

// ---------------------------------------------------------------------------
// Launch. Inputs (metadata order): x [B,H,S,D] f32, token_positions [S] i32,
// ro_weights [4096,128,128] f32. Output: [B,H,S,D] f32.
// ---------------------------------------------------------------------------
extern "C" void kernel_launch(void* const* d_in, const int* in_sizes, int n_in,
                              void* d_out, int out_size)
{
    const float* x          = (const float*)d_in[0];
    const int*   tok_pos    = (const int*)d_in[1];
    const float* ro_weights = (const float*)d_in[2];

    rope_fused_kernel<<<SEQ_LEN, THREADS>>>(
        reinterpret_cast<const float4*>(x),
        reinterpret_cast<float4*>((float*)d_out),
        ro_weights,
        tok_pos);
}